// round 17
// baseline (speedup 1.0000x reference)
#include <cuda_runtime.h>

// ---------------------------------------------------------------------------
//   x:  [2, 512, 512] complex (separate real/imag f32 planes)
//   P:  [128, 128] f32;  I: [2, 49, 128, 128] f32;  Ns: [49, 2] int32
//   out: float32 [2, 49, 512, 512] = REAL PART of complex grads (25,690,112)
//
// R16->R17: ONE mega-kernel. Clusters 0-1 (4 blocks each) run the serial
// chain (2 rows/warp ILP, I-prefetch before barrier). 88 worker blocks each
// own 1-2 kb tiles: spin on g_kdone[b], then run grad1+grad2 (register
// rdit512, R16-proven) for that tile. Grads fully overlap the chain.
// ---------------------------------------------------------------------------

#define NOBJ 512
#define MM   128
#define NCH  49
#define NB   2
#define CL   4                       // chain blocks per cluster (= per batch)
#define NWORK 88                     // worker blocks
#define GRID  (NB * CL + NWORK)      // 96, divisible by CL

__device__ float2 g_tw[256];                         // exp(+2*pi*i*k/512), k<256
__device__ float2 g_xFT[NB * NOBJ * NOBJ];           // 4 MB
__device__ float2 g_patch[NCH * NB * MM * MM];       // 12.8 MB  [kb][r][c]
__device__ float2 g_T[(size_t)NCH * NB * NOBJ * MM]; // 51.4 MB  [kb][t][c]
__device__ float2 g_W[NB * MM * MM];                 // step ping  [b][n1][j0]
__device__ float2 g_W2[NB * MM * MM];                // step pong  [b][m0][n1]
__device__ float  g_It[(size_t)NB * NCH * MM * MM];  // 6.4 MB: I transposed+brev
__device__ int    g_kdone[NB];                       // chain progress per batch

__device__ __forceinline__ int clampi(int i, int n) {
    return i < 0 ? 0 : (i >= n ? n - 1 : i);
}
__device__ __forceinline__ int brev7(int x) {
    return (int)(__brev((unsigned)x) >> 25);
}
__device__ __forceinline__ int brev9(int x) {
    return (int)(__brev((unsigned)x) >> 23);
}

#define CLUSTER_SYNC() do { \
    asm volatile("barrier.cluster.arrive.aligned;" ::: "memory"); \
    asm volatile("barrier.cluster.wait.aligned;" ::: "memory"); } while (0)

// ---------------------------------------------------------------------------
// Butterfly primitives (R15/R16-proven numerics).
// ---------------------------------------------------------------------------
template <bool INV>
__device__ __forceinline__ void dif_bfly(float2& x0, float2& x1, float2 w) {
    float wy = INV ? w.y : -w.y;
    float dx = x0.x - x1.x, dy = x0.y - x1.y;
    x0.x += x1.x; x0.y += x1.y;
    x1.x = w.x * dx - wy * dy;
    x1.y = w.x * dy + wy * dx;
}
template <bool INV>
__device__ __forceinline__ void dit_bfly(float2& x0, float2& x1, float2 w) {
    float wy = INV ? w.y : -w.y;
    float tx = w.x * x1.x - wy * x1.y;
    float ty = w.x * x1.y + wy * x1.x;
    x1.x = x0.x - tx; x1.y = x0.y - ty;
    x0.x += tx; x0.y += ty;
}
template <bool INV>
__device__ __forceinline__ void dif_shfl(float2 v[4], int half, float2 w, int lane) {
    float wy = INV ? w.y : -w.y;
    bool up = (lane & half) == 0;
#pragma unroll
    for (int q = 0; q < 4; q++) {
        float ox = __shfl_xor_sync(0xffffffffu, v[q].x, half);
        float oy = __shfl_xor_sync(0xffffffffu, v[q].y, half);
        float ax = v[q].x + ox, ay = v[q].y + oy;
        float dx = ox - v[q].x, dy = oy - v[q].y;
        float bx = w.x * dx - wy * dy, by = w.x * dy + wy * dx;
        v[q].x = up ? ax : bx;
        v[q].y = up ? ay : by;
    }
}
template <bool INV>
__device__ __forceinline__ void dit_shfl(float2 v[4], int half, float2 w, int lane) {
    float wy = INV ? w.y : -w.y;
    bool up = (lane & half) == 0;
#pragma unroll
    for (int q = 0; q < 4; q++) {
        float ox = __shfl_xor_sync(0xffffffffu, v[q].x, half);
        float oy = __shfl_xor_sync(0xffffffffu, v[q].y, half);
        float sx = up ? ox : v[q].x;
        float sy = up ? oy : v[q].y;
        float tx = w.x * sx - wy * sy;
        float ty = w.x * sy + wy * sx;
        float rx = up ? (v[q].x + tx) : (ox - tx);
        float ry = up ? (v[q].y + ty) : (oy - ty);
        v[q].x = rx; v[q].y = ry;
    }
}
template <bool INV>
__device__ __forceinline__ void dit_shfl16(float2 v[16], int half, float2 w, int lane) {
    float wy = INV ? w.y : -w.y;
    bool up = (lane & half) == 0;
#pragma unroll
    for (int q = 0; q < 16; q++) {
        float ox = __shfl_xor_sync(0xffffffffu, v[q].x, half);
        float oy = __shfl_xor_sync(0xffffffffu, v[q].y, half);
        float sx = up ? ox : v[q].x;
        float sy = up ? oy : v[q].y;
        float tx = w.x * sx - wy * sy;
        float ty = w.x * sy + wy * sx;
        float rx = up ? (v[q].x + tx) : (ox - tx);
        float ry = up ? (v[q].y + ty) : (oy - ty);
        v[q].x = rx; v[q].y = ry;
    }
}
template <bool INV>
__device__ __forceinline__ void rdif128(float2 v[4], const float2* T, int lane) {
    dif_bfly<INV>(v[0], v[2], T[0]);
    dif_bfly<INV>(v[1], v[3], T[1]);
    dif_bfly<INV>(v[0], v[1], T[2]);
    dif_bfly<INV>(v[2], v[3], T[2]);
    dif_shfl<INV>(v, 16, T[3], lane);
    dif_shfl<INV>(v, 8,  T[4], lane);
    dif_shfl<INV>(v, 4,  T[5], lane);
    dif_shfl<INV>(v, 2,  T[6], lane);
    dif_shfl<INV>(v, 1,  make_float2(1.f, 0.f), lane);
}
template <bool INV>
__device__ __forceinline__ void rdit128(float2 v[4], const float2* T, int lane) {
    dit_shfl<INV>(v, 1,  make_float2(1.f, 0.f), lane);
    dit_shfl<INV>(v, 2,  T[6], lane);
    dit_shfl<INV>(v, 4,  T[5], lane);
    dit_shfl<INV>(v, 8,  T[4], lane);
    dit_shfl<INV>(v, 16, T[3], lane);
    dit_bfly<INV>(v[0], v[1], T[2]);
    dit_bfly<INV>(v[2], v[3], T[2]);
    dit_bfly<INV>(v[0], v[2], T[0]);
    dit_bfly<INV>(v[1], v[3], T[1]);
}
// 512-pt register DIT (R16-proven): bitrev in, natural out.
template <bool INV>
__device__ __forceinline__ void rdit512(float2 v[16], const float2* tw, int lane) {
    dit_shfl16<INV>(v, 1,  make_float2(1.f, 0.f), lane);
    dit_shfl16<INV>(v, 2,  tw[(lane & 1) * 128], lane);
    dit_shfl16<INV>(v, 4,  tw[(lane & 3) * 64], lane);
    dit_shfl16<INV>(v, 8,  tw[(lane & 7) * 32], lane);
    dit_shfl16<INV>(v, 16, tw[(lane & 15) * 16], lane);
    {
        float2 w = tw[lane * 8];
#pragma unroll
        for (int q = 0; q < 16; q += 2) dit_bfly<INV>(v[q], v[q + 1], w);
    }
    {
        float2 w0 = tw[lane * 4];
        float2 w1 = tw[(32 + lane) * 4];
#pragma unroll
        for (int qb = 0; qb < 16; qb += 4) {
            dit_bfly<INV>(v[qb],     v[qb + 2], w0);
            dit_bfly<INV>(v[qb + 1], v[qb + 3], w1);
        }
    }
    {
        float2 w0 = tw[lane * 2];
        float2 w1 = tw[(32 + lane) * 2];
        float2 w2 = tw[(64 + lane) * 2];
        float2 w3 = tw[(96 + lane) * 2];
#pragma unroll
        for (int qb = 0; qb < 16; qb += 8) {
            dit_bfly<INV>(v[qb],     v[qb + 4], w0);
            dit_bfly<INV>(v[qb + 1], v[qb + 5], w1);
            dit_bfly<INV>(v[qb + 2], v[qb + 6], w2);
            dit_bfly<INV>(v[qb + 3], v[qb + 7], w3);
        }
    }
    {
#pragma unroll
        for (int q = 0; q < 8; q++) {
            float2 w = tw[q * 32 + lane];
            dit_bfly<INV>(v[q], v[q + 8], w);
        }
    }
}

// smem warp_fft (natural->natural) — init kernels (R10-proven).
template <int L, int LOGL, bool INV>
__device__ __forceinline__ void warp_fft(float2* a, const float2* tw) {
    const int lane = threadIdx.x & 31;
    constexpr int NPT = L / 32;
    float2 v[NPT];
#pragma unroll
    for (int q = 0; q < NPT; q++) {
        int idx = lane + (q << 5);
        int r = (int)(__brev((unsigned)idx) >> (32 - LOGL));
        v[q] = a[r];
    }
    __syncwarp();
#pragma unroll
    for (int q = 0; q < NPT; q++) a[lane + (q << 5)] = v[q];
    __syncwarp();
#pragma unroll
    for (int s = 1; s <= LOGL; s++) {
        const int half = 1 << (s - 1);
#pragma unroll
        for (int t = 0; t < (L >> 6); t++) {
            int j = lane + (t << 5);
            int pos = j & (half - 1);
            int i0 = ((j >> (s - 1)) << s) + pos;
            int i1 = i0 + half;
            float2 w = tw[pos << (9 - s)];
            float wy = INV ? w.y : -w.y;
            float2 x0 = a[i0], x1 = a[i1];
            float tr = w.x * x1.x - wy * x1.y;
            float ti = w.x * x1.y + wy * x1.x;
            a[i0] = make_float2(x0.x + tr, x0.y + ti);
            a[i1] = make_float2(x0.x - tr, x0.y - ti);
        }
        __syncwarp();
    }
}

__global__ void k_init_tw() {
    int k = threadIdx.x;
    double ang = 6.283185307179586476925286766559 * (double)k / 512.0;
    g_tw[k] = make_float2((float)cos(ang), (float)sin(ang));
}
__global__ void k_reset() {
    if (threadIdx.x < NB) g_kdone[threadIdx.x] = 0;
}
__global__ void __launch_bounds__(256) k_trI(const float* __restrict__ I) {
    int tile = blockIdx.x;
    const float* src = I + (size_t)tile * 16384;
    float* dst = g_It + (size_t)tile * 16384;
    for (int idx = threadIdx.x; idx < 16384; idx += 256) {
        int n1 = idx >> 7, e = idx & 127;
        dst[idx] = src[brev7(e) * 128 + n1];
    }
}

__global__ void __launch_bounds__(256) k_init_cols(const float* __restrict__ xr,
                                                   const float* __restrict__ xi,
                                                   int nx) {
    __shared__ float2 sm[8 * 520 + 256];
    float2* tw = sm + 8 * 520;
    int tid = threadIdx.x, w = tid >> 5, lane = tid & 31;
    tw[tid] = g_tw[tid];
    __syncthreads();
    int b = blockIdx.x >> 6;
    int c0 = (blockIdx.x & 63) << 3;
    int col = c0 + w;
    float2* a = sm + w * 520;
#pragma unroll
    for (int q = 0; q < 16; q++) {
        int j = lane + (q << 5);
        int idx = clampi(b * 262144 + j * 512 + col, nx);
        a[j] = make_float2(xr[idx], xi[idx]);
    }
    __syncwarp();
    warp_fft<512, 9, false>(a, tw);
    __syncthreads();
    for (int e = tid; e < 4096; e += 256) {
        int t = e >> 3, ww = e & 7;
        g_T[((size_t)b * 512 + t) * 512 + c0 + ww] = sm[ww * 520 + t];
    }
}

__global__ void __launch_bounds__(256) k_init_rows() {
    __shared__ float2 sm[8 * 520 + 256];
    float2* tw = sm + 8 * 520;
    int tid = threadIdx.x, w = tid >> 5, lane = tid & 31;
    tw[tid] = g_tw[tid];
    __syncthreads();
    int b = blockIdx.x >> 6;
    int f = ((blockIdx.x & 63) << 3) + w;
    float2* a = sm + w * 520;
    const float2* src = g_T + ((size_t)b * 512 + f) * 512;
#pragma unroll
    for (int q = 0; q < 16; q++) { int u = lane + (q << 5); a[u] = src[u]; }
    __syncwarp();
    warp_fft<512, 9, false>(a, tw);
    float2* dst = g_xFT + (size_t)b * 262144 + (size_t)f * 512;
#pragma unroll
    for (int q = 0; q < 16; q++) { int u = lane + (q << 5); dst[u] = a[u]; }
}

// ---------------------------------------------------------------------------
// Mega-kernel: clusters 0-1 = chain (4 blocks/batch, 2 rows/warp);
// blocks 8..95 = grad workers (1-2 kb tiles each).
// Dynamic smem pool: chain uses 32*132 float2; worker grad1 park 16*520.
// ---------------------------------------------------------------------------
__global__ void __launch_bounds__(512, 1) __cluster_dims__(CL, 1, 1)
k_fused(const float* __restrict__ P, const int* __restrict__ Ns, int nns,
        float* __restrict__ outf, int n_out) {
    extern __shared__ float2 pool[];      // >= 16*520 float2
    __shared__ float2 tws[256];
    int tid = threadIdx.x, w = tid >> 5, lane = tid & 31;
    if (tid < 256) tws[tid] = g_tw[tid];
    __syncthreads();

    int cid = blockIdx.x >> 2;            // cluster id

    if (cid < NB) {
        // ===================== CHAIN =====================
        int b = cid;
        int blk = blockIdx.x & 3;
        int rowbase = blk << 5;           // 32 rows per block
        float2* sm = pool;                // [32][132]
        float2* xft = g_xFT + (size_t)b * 262144;
        float2* Wb = g_W + (size_t)b * 16384;
        float2* W2b = g_W2 + (size_t)b * 16384;
        const float sA = 1.0f / 262144.0f;

        float2 T[7];
        T[0] = g_tw[lane * 4];
        T[1] = g_tw[(lane + 32) * 4];
        T[2] = g_tw[lane * 8];
        T[3] = g_tw[(lane & 15) * 16];
        T[4] = g_tw[(lane & 7) * 32];
        T[5] = g_tw[(lane & 3) * 64];
        T[6] = g_tw[(lane & 1) * 128];

        int row0 = rowbase + w;           // warp's two rows/cols
        int row1 = rowbase + w + 16;
        float2 v[4];

        for (int k = 0; k < NCH; k++) {
            int kxl = 192 + Ns[2 * k];
            int kyl = 192 + Ns[2 * k + 1];

            // prefetch I for phase 2 (pure input)
            float Ip[2][4];
            {
                const float* Ikt = g_It + ((size_t)(b * NCH + k) << 14);
#pragma unroll
                for (int q = 0; q < 4; q++) {
                    Ip[0][q] = Ikt[row0 * 128 + (q << 5) + lane];
                    Ip[1][q] = Ikt[row1 * 128 + (q << 5) + lane];
                }
            }

            // ---- phase 1: window*P -> row IFFT(DIF) -> W^T ----
#pragma unroll
            for (int rr = 0; rr < 2; rr++) {
                int j0 = rr ? row1 : row0;
                int r = (j0 + 64) & 127;
                int u0 = (kxl + r + 256) & 511;
                const float2* xrow = xft + (size_t)u0 * 512;
                const float* prow = P + r * 128;
#pragma unroll
                for (int q = 0; q < 4; q++) {
                    int j1 = (q << 5) + lane;
                    int c = j1 ^ 64;
                    int u1 = (kyl + c + 256) & 511;
                    float2 xv = __ldcg(&xrow[u1]);
                    float p = prow[c];
                    v[q] = make_float2(xv.x * p, xv.y * p);
                }
                rdif128<true>(v, T, lane);
#pragma unroll
                for (int q = 0; q < 4; q++)
                    sm[(j0 - rowbase) * 132 + brev7((q << 5) + lane)] = v[q];
            }
            __syncthreads();
            for (int e = tid; e < 4096; e += 512) {
                int n1 = e >> 5, rl = e & 31;
                Wb[n1 * 128 + rowbase + rl] = sm[rl * 132 + n1];
            }
            CLUSTER_SYNC();

            // ---- phase 2: col IFFT(DIF) -> nonlin -> col FFT(DIT) -> W2^T --
#pragma unroll
            for (int rr = 0; rr < 2; rr++) {
                int n1 = rr ? row1 : row0;
                const float2* src = Wb + (size_t)n1 * 128;
#pragma unroll
                for (int q = 0; q < 4; q++) v[q] = __ldcg(&src[(q << 5) + lane]);
                rdif128<true>(v, T, lane);
#pragma unroll
                for (int q = 0; q < 4; q++) {
                    float vr = v[q].x * sA, vi = v[q].y * sA;
                    float m = vr * vr + vi * vi - Ip[rr][q];
                    v[q] = make_float2(m * vr, m * vi);
                }
                rdit128<false>(v, T, lane);
#pragma unroll
                for (int q = 0; q < 4; q++)
                    sm[(n1 - rowbase) * 132 + (q << 5) + lane] = v[q];
            }
            __syncthreads();
            for (int e = tid; e < 4096; e += 512) {
                int m0 = e >> 5, rl = e & 31;
                W2b[m0 * 128 + rowbase + rl] = sm[rl * 132 + m0];
            }
            CLUSTER_SYNC();

            // ---- phase 3: row FFT(DIF) -> patch; update xFT ----
            int kb = k * NB + b;
#pragma unroll
            for (int rr = 0; rr < 2; rr++) {
                int m0 = rr ? row1 : row0;
                const float2* src = W2b + (size_t)m0 * 128;
#pragma unroll
                for (int q = 0; q < 4; q++) v[q] = __ldcg(&src[(q << 5) + lane]);
                rdif128<false>(v, T, lane);
#pragma unroll
                for (int q = 0; q < 4; q++)
                    sm[(m0 - rowbase) * 132 + brev7((q << 5) + lane)] = v[q];
                __syncwarp();
                int r = (m0 + 64) & 127;
                int u0 = (kxl + r + 256) & 511;
                float2* patch_row = g_patch + (size_t)kb * 16384 + r * 128;
                float2* xrow = xft + (size_t)u0 * 512;
                const float* prow = P + r * 128;
#pragma unroll
                for (int q = 0; q < 4; q++) {
                    int m1 = (q << 5) + lane;
                    int c = m1 ^ 64;
                    float2 f = sm[(m0 - rowbase) * 132 + m1];
                    float p = prow[c];
                    float2 patch = make_float2(f.x * p, f.y * p);
                    patch_row[c] = patch;
                    int u1 = (kyl + c + 256) & 511;
                    float2 xv = __ldcg(&xrow[u1]);
                    xrow[u1] = make_float2(xv.x - 0.16f * patch.x,
                                           xv.y - 0.16f * patch.y);
                }
            }
            __threadfence();              // patch -> device scope for workers
            CLUSTER_SYNC();
            if (blk == 0 && tid == 0) atomicAdd(&g_kdone[b], 1);
        }
    } else {
        // ===================== GRAD WORKERS =====================
        int wid = blockIdx.x - NB * CL;   // 0..NWORK-1
        float2* park = pool;              // [16][520]
        for (int pass = 0; pass < 2; pass++) {
            int kb = (pass == 0) ? wid : (NWORK + wid);
            if (kb >= NCH * NB) break;
            int k = kb >> 1, b = kb & 1;

            // wait for chain step k of batch b
            if (tid == 0) {
                volatile int* p = &g_kdone[b];
                while (*p <= k) __nanosleep(200);
                __threadfence();
            }
            __syncthreads();

            int off0 = (192 + Ns[clampi(2 * k, nns)] + 256) & 511;
            int off1 = (192 + Ns[clampi(2 * k + 1, nns)] + 256) & 511;
            const float2* patch = g_patch + (size_t)kb * 16384;
            float2 v[16];

            // grad1: 128 columns, 16 warps -> 8 iterations
            for (int ci = 0; ci < 8; ci++) {
                int c0 = ci << 4;
                int c = c0 + w;
#pragma unroll
                for (int q = 0; q < 16; q++) {
                    int p = (q << 5) + lane;
                    int j = brev9(p);
                    int r = (j - off0) & 511;
                    v[q] = (r < 128) ? patch[r * 128 + c] : make_float2(0.f, 0.f);
                }
                rdit512<true>(v, tws, lane);
#pragma unroll
                for (int q = 0; q < 16; q++) park[w * 520 + (q << 5) + lane] = v[q];
                __syncthreads();
                for (int e = tid; e < 8192; e += 512) {
                    int t = e >> 4, ww = e & 15;
                    g_T[((size_t)kb * 512 + t) * 128 + c0 + ww] = park[ww * 520 + t];
                }
                __syncthreads();
            }

            // grad2: 512 rows, 16 warps -> 32 iterations
            const float s = 1.0f / 16384.0f;
            for (int ti = 0; ti < 32; ti++) {
                int t = (ti << 4) + w;
                const float2* src = g_T + ((size_t)kb * 512 + t) * 128;
#pragma unroll
                for (int q = 0; q < 16; q++) {
                    int p = (q << 5) + lane;
                    int j = brev9(p);
                    int c = (j - off1) & 511;
                    v[q] = (c < 128) ? src[c] : make_float2(0.f, 0.f);
                }
                rdit512<true>(v, tws, lane);
                long long base = (((long long)b * NCH + k) * 512 + t) * 512;
#pragma unroll
                for (int q = 0; q < 16; q++) {
                    long long idx = base + (q << 5) + lane;
                    if (idx < (long long)n_out) outf[idx] = v[q].x * s;
                }
            }
        }
    }
}

// ---------------------------------------------------------------------------
extern "C" void kernel_launch(void* const* d_in, const int* in_sizes, int n_in,
                              void* d_out, int out_size) {
    const float *xr = nullptr, *xi = nullptr, *P = nullptr, *I = nullptr;
    const int* Ns = nullptr;
    int nx = 0, nns = 0;
    for (int i = 0; i < n_in; i++) {
        int sz = in_sizes[i];
        if (sz == 524288) {
            if (!xr) { xr = (const float*)d_in[i]; nx = sz; }
            else if (!xi) xi = (const float*)d_in[i];
        } else if (sz == 16384) { P = (const float*)d_in[i]; }
        else if (sz == 1605632) { I = (const float*)d_in[i]; }
        else if (sz == 98)      { Ns = (const int*)d_in[i]; nns = sz; }
    }
    if (!xr || !xi || !P || !I || !Ns) return;
    float* outf = (float*)d_out;

    const int fused_smem = 16 * 520 * sizeof(float2);   // 66560 B
    cudaFuncSetAttribute(k_fused, cudaFuncAttributeMaxDynamicSharedMemorySize,
                         fused_smem);

    k_init_tw<<<1, 256>>>();
    k_trI<<<NB * NCH, 256>>>(I);
    k_init_cols<<<128, 256>>>(xr, xi, nx);
    k_init_rows<<<128, 256>>>();
    k_reset<<<1, 32>>>();
    k_fused<<<GRID, 512, fused_smem>>>(P, Ns, nns, outf, out_size);
}